// round 14
// baseline (speedup 1.0000x reference)
#include <cuda_runtime.h>
#include <cuda_fp16.h>
#include <mma.h>
#include <cstdint>

using namespace nvcuda;

// Problem constants
#define NB    1024   // batch
#define BT    256    // block_size (seq len)
#define CE    384    // n_embed
#define HS    64     // head_size

// Scratch (device globals: no allocation allowed)
__device__ float g_q[(size_t)NB * BT * HS];
__device__ float g_k[(size_t)NB * BT * HS];
__device__ float g_v[(size_t)NB * BT * HS];
// Combined fp16 weights: [CE][192] where cols = [Wq | Wk | Wv]
__device__ __half g_wh[CE * 192];

// ---------------------------------------------------------------------------
// helpers
// ---------------------------------------------------------------------------
__device__ __forceinline__ uint32_t smem_u32(const void* p) {
    uint32_t a;
    asm("{ .reg .u64 t; cvta.to.shared.u64 t, %1; cvt.u32.u64 %0, t; }"
        : "=r"(a) : "l"(p));
    return a;
}
__device__ __forceinline__ void cp_async16(uint32_t dst, const void* src) {
    asm volatile("cp.async.ca.shared.global [%0], [%1], 16;"
                 :: "r"(dst), "l"(src) : "memory");
}
__device__ __forceinline__ void cp_commit() {
    asm volatile("cp.async.commit_group;" ::: "memory");
}
template <int N>
__device__ __forceinline__ void cp_wait() {
    asm volatile("cp.async.wait_group %0;" :: "n"(N) : "memory");
}

// Fast exp on the FMA pipe (no MUFU). |rel err| ~2.4e-6.
__device__ __forceinline__ float fast_exp(float x) {
    x = fmaxf(x, -87.0f);
    float r = x * 1.4426950408889634f;
    float kf = r + 12582912.0f;                 // 1.5*2^23 round-to-nearest
    float i  = kf - 12582912.0f;
    float f  = r - i;
    float p = 0.0013333558f;
    p = fmaf(p, f, 0.0096181291f);
    p = fmaf(p, f, 0.0555041087f);
    p = fmaf(p, f, 0.2402265069f);
    p = fmaf(p, f, 0.6931471806f);
    p = fmaf(p, f, 1.0f);
    int ik = __float_as_int(kf) - 0x4B400000;
    float scale = __int_as_float((ik + 127) << 23);
    return p * scale;
}

// mma.sync m16n8k16 fp16 -> fp32 (baseline PTX, valid on sm_103)
__device__ __forceinline__ void mma16816(float* c, const uint32_t* a, const uint32_t* b) {
    asm volatile(
        "mma.sync.aligned.m16n8k16.row.col.f32.f16.f16.f32 "
        "{%0,%1,%2,%3}, {%4,%5,%6,%7}, {%8,%9}, {%0,%1,%2,%3};"
        : "+f"(c[0]), "+f"(c[1]), "+f"(c[2]), "+f"(c[3])
        : "r"(a[0]), "r"(a[1]), "r"(a[2]), "r"(a[3]), "r"(b[0]), "r"(b[1]));
}
__device__ __forceinline__ void ldsm_x4(uint32_t* r, uint32_t addr) {
    asm volatile("ldmatrix.sync.aligned.m8n8.x4.shared.b16 {%0,%1,%2,%3}, [%4];"
                 : "=r"(r[0]), "=r"(r[1]), "=r"(r[2]), "=r"(r[3]) : "r"(addr));
}
__device__ __forceinline__ void ldsm_x4_t(uint32_t* r, uint32_t addr) {
    asm volatile("ldmatrix.sync.aligned.m8n8.x4.trans.shared.b16 {%0,%1,%2,%3}, [%4];"
                 : "=r"(r[0]), "=r"(r[1]), "=r"(r[2]), "=r"(r[3]) : "r"(addr));
}
__device__ __forceinline__ uint32_t pack_h2(__half a, __half b) {
    __half2 t = __halves2half2(a, b);
    return *reinterpret_cast<uint32_t*>(&t);
}

// ---------------------------------------------------------------------------
// Kernel 0: convert W (q,k,v) into combined fp16 [CE][192].
// ---------------------------------------------------------------------------
__global__ void wconv_kernel(const float* __restrict__ Wq,
                             const float* __restrict__ Wk,
                             const float* __restrict__ Wv) {
    int i = blockIdx.x * blockDim.x + threadIdx.x;
    if (i >= 3 * CE * HS) return;
    int w = i / (CE * HS);
    int r = i % (CE * HS);
    int k = r / HS;
    int n = r % HS;
    const float* W = (w == 0) ? Wq : (w == 1) ? Wk : Wv;
    g_wh[k * 192 + w * 64 + n] = __float2half_rn(W[k * HS + n]);
}

// ---------------------------------------------------------------------------
// Kernel 1: QKV projection (WMMA fp16, single-term), 3-stage pipeline.
// S (fp32 x) and B (fp16 W): 3-stage cp.async rings (prefetch distance 2).
// A (fp16 x): 2-stage; convert(kc+1) hoisted before MMA(kc) so its LDS
// latency interleaves with HMMA issue. ONE barrier per chunk.
// ---------------------------------------------------------------------------
#define AST2 72
#define A_HALFS (128 * AST2)                   // 9216 halfs per A stage
#define BST 200
#define B_STG (64 * BST)                       // 12800 halfs per B stage
#define PS_OFF_B ((2 * A_HALFS + 3 * B_STG) * 2)   // 113664 B
#define S_FLOATS 8192                          // floats per S stage
#define P_SMEM_BYTES (PS_OFF_B + 3 * S_FLOATS * 4) // 211968 B

__global__ __launch_bounds__(384) void qkv_proj_wmma(const float* __restrict__ x)
{
    extern __shared__ __align__(16) char smp[];
    __half* A  = (__half*)smp;
    __half* Bb = A + 2 * A_HALFS;
    float*  S  = (float*)(smp + PS_OFF_B);

    const int tid = threadIdx.x;
    const int wrp = tid >> 5;
    const int wym = wrp / 3;
    const int wxn = wrp % 3;
    const size_t rowBase = (size_t)blockIdx.x * 128;
    const uint32_t sB = smem_u32(Bb);
    const uint32_t sS = smem_u32(S);

    wmma::fragment<wmma::accumulator, 16, 16, 16, float> acc[2][4];
    #pragma unroll
    for (int i = 0; i < 2; ++i)
        #pragma unroll
        for (int j = 0; j < 4; ++j)
            wmma::fill_fragment(acc[i][j], 0.0f);

    // issue chunk kc: S into stage kc%3 (fp32 x) + B into stage kc%3, one group
    auto issueChunk = [&](int kc) {
        int st = kc % 3;
        #pragma unroll
        for (int p = 0; p < 6; ++p) {
            int i = tid + p * 384;             // 2048 float4
            if (i < 2048) {
                int r  = i >> 4;
                int c4 = i & 15;
                cp_async16(sS + (uint32_t)(st * S_FLOATS + r * 64 + c4 * 4) * 4,
                           x + (rowBase + r) * CE + kc * 64 + c4 * 4);
            }
        }
        #pragma unroll
        for (int p = 0; p < 4; ++p) {
            int i = tid + p * 384;             // 1536 x 16B
            int r = i / 24;
            int c = i % 24;
            cp_async16(sB + (uint32_t)(st * B_STG + r * BST + c * 8) * 2,
                       g_wh + (size_t)(kc * 64 + r) * 192 + c * 8);
        }
        cp_commit();
    };
    // convert chunk kc1 from S[kc1%3] (fp32) into A stage ab (fp16)
    auto convertChunk = [&](int kc1, int ab) {
        const float* Ss = S + (kc1 % 3) * S_FLOATS;
        __half* Ad = A + ab * A_HALFS;
        #pragma unroll
        for (int p = 0; p < 6; ++p) {
            int i = tid + p * 384;
            if (i < 2048) {
                int r  = i >> 4;
                int c4 = i & 15;
                float4 v = *(const float4*)&Ss[r * 64 + c4 * 4];
                __half* d = Ad + r * AST2 + c4 * 4;
                ((__half2*)d)[0] = __floats2half2_rn(v.x, v.y);
                ((__half2*)d)[1] = __floats2half2_rn(v.z, v.w);
            }
        }
    };

    // prologue: groups 0,1 in flight; convert chunk 0; group 2 in flight
    issueChunk(0);
    issueChunk(1);
    cp_wait<1>();            // group 0 arrived (group 1 may fly)
    convertChunk(0, 0);      // own-thread cp.async data: no barrier needed
    issueChunk(2);
    __syncthreads();         // A[0] visible to all warps

    for (int kc = 0; kc < 6; ++kc) {
        const int abuf = kc & 1;
        if (kc < 5) {
            // group(kc+1) arrived; group(kc+2) may still fly (none beyond)
            if (kc < 4) cp_wait<1>(); else cp_wait<0>();
            convertChunk(kc + 1, abuf ^ 1);   // overlaps with MMA(kc) below
        }

        const __half* aS = A + abuf * A_HALFS;
        const __half* bS = Bb + (kc % 3) * B_STG;
        #pragma unroll
        for (int ks = 0; ks < 4; ++ks) {
            wmma::fragment<wmma::matrix_a, 16, 16, 16, __half, wmma::row_major> a[2];
            wmma::fragment<wmma::matrix_b, 16, 16, 16, __half, wmma::row_major> b[4];
            #pragma unroll
            for (int i = 0; i < 2; ++i)
                wmma::load_matrix_sync(a[i], aS + (wym * 32 + i * 16) * AST2 + ks * 16, AST2);
            #pragma unroll
            for (int j = 0; j < 4; ++j)
                wmma::load_matrix_sync(b[j], bS + (ks * 16) * BST + wxn * 64 + j * 16, BST);
            #pragma unroll
            for (int i = 0; i < 2; ++i)
                #pragma unroll
                for (int j = 0; j < 4; ++j)
                    wmma::mma_sync(acc[i][j], a[i], b[j], acc[i][j]);
        }
        __syncthreads();     // A[abuf^1] now visible; stage kc%3 readers done
        if (kc < 3) issueChunk(kc + 3);   // reuse stage kc%3 (just retired)
    }

    // epilogue: each warp's 64-col range is exactly one of q/k/v
    float* dst = (wxn == 0) ? g_q : (wxn == 1) ? g_k : g_v;
    #pragma unroll
    for (int i = 0; i < 2; ++i) {
        size_t row = rowBase + wym * 32 + i * 16;
        #pragma unroll
        for (int j = 0; j < 4; ++j)
            wmma::store_matrix_sync(dst + row * HS + j * 16, acc[i][j], HS,
                                    wmma::mem_row_major);
    }
}

// ---------------------------------------------------------------------------
// Kernel 2: causal flash attention (split-fp16, raw mma.sync) — R13 verbatim.
// QK^T: 2-term (qh*kh + qh*kl). PV: 2-term (Ph*Vh + Ph*Vl).
// __launch_bounds__(256, 2): 2 CTAs/SM for latency hiding.
// ---------------------------------------------------------------------------
#define KST 72
#define C_HALFS (256 * KST)                       // 18432 halfs = 36864 B
#define AS_OFF_B (C_HALFS * 2)                    // byte offset of S
#define ATT_SMEM_BYTES (AS_OFF_B + 8192 * 4)      // 69632 B

__global__ __launch_bounds__(256, 2) void attn_mma(float* __restrict__ out)
{
    extern __shared__ __align__(16) char smc[];
    __half* C = (__half*)smc;
    float*  S = (float*)(smc + AS_OFF_B);

    const int tid  = threadIdx.x;
    const int lane = tid & 31;
    const int w    = tid >> 5;
    const int b    = blockIdx.y;
    const int qt2  = blockIdx.x;               // 0..1 (128-row q block)
    const int nt   = qt2 * 2 + 2;              // key tiles to process
    const size_t qrow0 = (size_t)b * BT + qt2 * 128;
    const float scale = 0.05103103630798288f;  // 384^-0.5
    const uint32_t sb = smem_u32(C);
    const uint32_t sS = smem_u32(S);

    auto issueS = [&](int st) {
        #pragma unroll
        for (int p = 0; p < 8; ++p) {
            int i   = tid + p * 256;           // 2048 x 16B
            int arr = i >> 10;                 // 0: k, 1: v
            int r   = (i >> 4) & 63;
            int c4  = i & 15;
            const float* src = (arr ? g_v : g_k)
                               + ((size_t)b * BT + st * 64 + r) * HS + c4 * 4;
            cp_async16(sS + (uint32_t)(arr * 4096 + r * 64 + c4 * 4) * 4, src);
        }
        cp_commit();
    };

    issueS(0);   // tile-0 loads in flight while Q stages

    // --- stage Q (direct LDG fp32 -> fp16 hi only, into C rows 0..127) ---
    #pragma unroll
    for (int p = 0; p < 8; ++p) {
        int i  = tid + p * 256;                // 0..2047
        int r  = i >> 4;                       // 0..127
        int c4 = i & 15;
        float4 v = *(const float4*)(g_q + (qrow0 + r) * HS + c4 * 4);
        __half* dh = C + r * KST + c4 * 4;
        ((__half2*)dh)[0] = __floats2half2_rn(v.x, v.y);
        ((__half2*)dh)[1] = __floats2half2_rn(v.z, v.w);
    }
    __syncthreads();

    // --- Q fragments (fp16, held in registers across the whole key loop) ---
    uint32_t qh[4][4];
    const int wrow = w * 16;
    {
        int sub = lane >> 3, r8 = lane & 7;
        int rloc = wrow + (sub & 1) * 8 + r8;
        uint32_t ah_ = sb + (uint32_t)(rloc * KST) * 2 + (sub >> 1) * 16;
        #pragma unroll
        for (int kk = 0; kk < 4; ++kk)
            ldsm_x4(qh[kk], ah_ + kk * 32);
    }

    float o[8][4];
    #pragma unroll
    for (int t = 0; t < 8; ++t)
        #pragma unroll
        for (int i = 0; i < 4; ++i) o[t][i] = 0.0f;
    float m_lo = -1e30f, m_hi = -1e30f, l_lo = 0.0f, l_hi = 0.0f;

    const int growmin = qt2 * 128 + wrow;
    const int growmax = growmin + 15;
    const int grow_lo = growmin + (lane >> 2);
    const int grow_hi = grow_lo + 8;

    const uint32_t kh_b = sb;
    const uint32_t kl_b = sb + (uint32_t)(64 * KST) * 2;
    const uint32_t vh_b = sb + (uint32_t)(128 * KST) * 2;
    const uint32_t vl_b = sb + (uint32_t)(192 * KST) * 2;

    for (int st = 0; st < nt; ++st) {
        cp_wait<0>();
        __syncthreads();       // S visible to all; all reads of C done

        // --- convert S (fp32) -> C (fp16 hi/lo) ---
        #pragma unroll
        for (int p = 0; p < 8; ++p) {
            int i   = tid + p * 256;           // 2048 float4
            int arr = i >> 10;                 // 0: k, 1: v
            int r   = (i >> 4) & 63;
            int c4  = i & 15;
            float4 v = *(const float4*)&S[arr * 4096 + r * 64 + c4 * 4];
            float hx = __half2float(__float2half_rn(v.x));
            float hy = __half2float(__float2half_rn(v.y));
            float hz = __half2float(__float2half_rn(v.z));
            float hw = __half2float(__float2half_rn(v.w));
            __half* dh = C + (arr * 128 + r) * KST + c4 * 4;
            __half* dl = C + (arr * 128 + 64 + r) * KST + c4 * 4;
            ((__half2*)dh)[0] = __floats2half2_rn(v.x, v.y);
            ((__half2*)dh)[1] = __floats2half2_rn(v.z, v.w);
            ((__half2*)dl)[0] = __floats2half2_rn(v.x - hx, v.y - hy);
            ((__half2*)dl)[1] = __floats2half2_rn(v.z - hz, v.w - hw);
        }
        __syncthreads();       // C ready; S free
        if (st + 1 < nt) issueS(st + 1);   // loads for next tile fly under compute

        if (st * 64 <= growmax) {
            // --- S = Q K^T (2-term: qh*kh + qh*kl) ---
            float c[8][4];
            #pragma unroll
            for (int t = 0; t < 8; ++t)
                #pragma unroll
                for (int i = 0; i < 4; ++i) c[t][i] = 0.0f;

            {
                int sub = lane >> 3, r8 = lane & 7;
                #pragma unroll
                for (int kk = 0; kk < 4; ++kk) {
                    #pragma unroll
                    for (int tp = 0; tp < 4; ++tp) {
                        int krow = (2 * tp + (sub >> 1)) * 8 + r8;
                        uint32_t off = kk * 32 + (sub & 1) * 16;
                        uint32_t bh4[4], bl4[4];
                        ldsm_x4(bh4, kh_b + (uint32_t)(krow * KST) * 2 + off);
                        ldsm_x4(bl4, kl_b + (uint32_t)(krow * KST) * 2 + off);
                        #pragma unroll
                        for (int tt = 0; tt < 2; ++tt) {
                            int t = 2 * tp + tt;
                            mma16816(c[t], qh[kk], &bh4[2 * tt]);
                            mma16816(c[t], qh[kk], &bl4[2 * tt]);
                        }
                    }
                }
            }

            // --- scale + causal mask ---
            #pragma unroll
            for (int t = 0; t < 8; ++t)
                #pragma unroll
                for (int i = 0; i < 4; ++i) c[t][i] *= scale;

            if (st * 64 + 63 > growmin) {
                int colb = st * 64 + 2 * (lane & 3);
                #pragma unroll
                for (int t = 0; t < 8; ++t) {
                    int c0 = colb + 8 * t, c1 = c0 + 1;
                    if (c0 > grow_lo) c[t][0] = -1e30f;
                    if (c1 > grow_lo) c[t][1] = -1e30f;
                    if (c0 > grow_hi) c[t][2] = -1e30f;
                    if (c1 > grow_hi) c[t][3] = -1e30f;
                }
            }

            // --- online softmax in registers ---
            float mx0 = -1e30f, mx1 = -1e30f;
            #pragma unroll
            for (int t = 0; t < 8; ++t) {
                mx0 = fmaxf(mx0, fmaxf(c[t][0], c[t][1]));
                mx1 = fmaxf(mx1, fmaxf(c[t][2], c[t][3]));
            }
            mx0 = fmaxf(mx0, __shfl_xor_sync(0xffffffffu, mx0, 1, 4));
            mx0 = fmaxf(mx0, __shfl_xor_sync(0xffffffffu, mx0, 2, 4));
            mx1 = fmaxf(mx1, __shfl_xor_sync(0xffffffffu, mx1, 1, 4));
            mx1 = fmaxf(mx1, __shfl_xor_sync(0xffffffffu, mx1, 2, 4));
            float mn0 = fmaxf(m_lo, mx0), mn1 = fmaxf(m_hi, mx1);
            float al0 = fast_exp(m_lo - mn0), al1 = fast_exp(m_hi - mn1);
            m_lo = mn0; m_hi = mn1;

            float s0 = 0.0f, s1 = 0.0f;
            #pragma unroll
            for (int t = 0; t < 8; ++t) {
                c[t][0] = fast_exp(c[t][0] - mn0); s0 += c[t][0];
                c[t][1] = fast_exp(c[t][1] - mn0); s0 += c[t][1];
                c[t][2] = fast_exp(c[t][2] - mn1); s1 += c[t][2];
                c[t][3] = fast_exp(c[t][3] - mn1); s1 += c[t][3];
            }
            s0 += __shfl_xor_sync(0xffffffffu, s0, 1, 4);
            s0 += __shfl_xor_sync(0xffffffffu, s0, 2, 4);
            s1 += __shfl_xor_sync(0xffffffffu, s1, 1, 4);
            s1 += __shfl_xor_sync(0xffffffffu, s1, 2, 4);
            l_lo = l_lo * al0 + s0;
            l_hi = l_hi * al1 + s1;
            #pragma unroll
            for (int t = 0; t < 8; ++t) {
                o[t][0] *= al0; o[t][1] *= al0;
                o[t][2] *= al1; o[t][3] *= al1;
            }

            // --- O += P V (2-term: Ph*Vh + Ph*Vl) ---
            {
                int sub = lane >> 3, r8 = lane & 7;
                #pragma unroll
                for (int kv = 0; kv < 4; ++kv) {
                    uint32_t af_h[4];
                    #pragma unroll
                    for (int half = 0; half < 2; ++half) {
                        int tt = 2 * kv + half;
                        af_h[half * 2 + 0] = pack_h2(__float2half_rn(c[tt][0]),
                                                     __float2half_rn(c[tt][1]));
                        af_h[half * 2 + 1] = pack_h2(__float2half_rn(c[tt][2]),
                                                     __float2half_rn(c[tt][3]));
                    }

                    int vrow = kv * 16 + (sub & 1) * 8 + r8;
                    #pragma unroll
                    for (int tp = 0; tp < 4; ++tp) {
                        uint32_t off = 16 * (2 * tp + (sub >> 1));
                        uint32_t vh4[4], vl4[4];
                        ldsm_x4_t(vh4, vh_b + (uint32_t)(vrow * KST) * 2 + off);
                        ldsm_x4_t(vl4, vl_b + (uint32_t)(vrow * KST) * 2 + off);
                        #pragma unroll
                        for (int tt = 0; tt < 2; ++tt) {
                            int t = 2 * tp + tt;
                            mma16816(o[t], af_h, &vh4[2 * tt]);
                            mma16816(o[t], af_h, &vl4[2 * tt]);
                        }
                    }
                }
            }
        }
    }

    // --- epilogue: normalize by 1/l, write out ---
    float inv0 = 1.0f / l_lo, inv1 = 1.0f / l_hi;
    int rlo = wrow + (lane >> 2);
    size_t base_lo = (qrow0 + rlo) * HS + 2 * (lane & 3);
    size_t base_hi = (qrow0 + rlo + 8) * HS + 2 * (lane & 3);
    #pragma unroll
    for (int t = 0; t < 8; ++t) {
        *(float2*)(out + base_lo + 8 * t) = make_float2(o[t][0] * inv0, o[t][1] * inv0);
        *(float2*)(out + base_hi + 8 * t) = make_float2(o[t][2] * inv1, o[t][3] * inv1);
    }
}

// ---------------------------------------------------------------------------
// Launch
// ---------------------------------------------------------------------------
extern "C" void kernel_launch(void* const* d_in, const int* in_sizes, int n_in,
                              void* d_out, int out_size)
{
    (void)in_sizes; (void)n_in; (void)out_size;
    const float* x  = (const float*)d_in[0];
    const float* Wq = (const float*)d_in[1];
    const float* Wk = (const float*)d_in[2];
    const float* Wv = (const float*)d_in[3];
    float* out = (float*)d_out;

    cudaFuncSetAttribute(qkv_proj_wmma,
                         cudaFuncAttributeMaxDynamicSharedMemorySize,
                         P_SMEM_BYTES);
    cudaFuncSetAttribute(attn_mma,
                         cudaFuncAttributeMaxDynamicSharedMemorySize,
                         ATT_SMEM_BYTES);

    // W -> combined fp16
    wconv_kernel<<<(3 * CE * HS + 255) / 256, 256>>>(Wq, Wk, Wv);

    // QKV projection on tensor cores: 262144 rows / 128 per CTA = 2048 CTAs
    qkv_proj_wmma<<<2048, 384, P_SMEM_BYTES>>>(x);

    // Attention: 2 q-blocks of 128 rows x 1024 batches
    attn_mma<<<dim3(2, NB), 256, ATT_SMEM_BYTES>>>(out);
}

// round 15
// speedup vs baseline: 1.3396x; 1.3396x over previous
#include <cuda_runtime.h>
#include <cuda_fp16.h>
#include <mma.h>
#include <cstdint>

using namespace nvcuda;

// Problem constants
#define NB    1024   // batch
#define BT    256    // block_size (seq len)
#define CE    384    // n_embed
#define HS    64     // head_size

// Scratch (device globals: no allocation allowed)
__device__ float g_q[(size_t)NB * BT * HS];
__device__ float g_k[(size_t)NB * BT * HS];
__device__ float g_v[(size_t)NB * BT * HS];
// Combined fp16 weights: [CE][192] where cols = [Wq | Wk | Wv]
__device__ __half g_wh[CE * 192];

// ---------------------------------------------------------------------------
// helpers
// ---------------------------------------------------------------------------
__device__ __forceinline__ uint32_t smem_u32(const void* p) {
    uint32_t a;
    asm("{ .reg .u64 t; cvta.to.shared.u64 t, %1; cvt.u32.u64 %0, t; }"
        : "=r"(a) : "l"(p));
    return a;
}
__device__ __forceinline__ void cp_async16(uint32_t dst, const void* src) {
    asm volatile("cp.async.ca.shared.global [%0], [%1], 16;"
                 :: "r"(dst), "l"(src) : "memory");
}
__device__ __forceinline__ void cp_commit() {
    asm volatile("cp.async.commit_group;" ::: "memory");
}
template <int N>
__device__ __forceinline__ void cp_wait() {
    asm volatile("cp.async.wait_group %0;" :: "n"(N) : "memory");
}

// Fast exp on the FMA pipe (no MUFU). |rel err| ~2.4e-6.
__device__ __forceinline__ float fast_exp(float x) {
    x = fmaxf(x, -87.0f);
    float r = x * 1.4426950408889634f;
    float kf = r + 12582912.0f;                 // 1.5*2^23 round-to-nearest
    float i  = kf - 12582912.0f;
    float f  = r - i;
    float p = 0.0013333558f;
    p = fmaf(p, f, 0.0096181291f);
    p = fmaf(p, f, 0.0555041087f);
    p = fmaf(p, f, 0.2402265069f);
    p = fmaf(p, f, 0.6931471806f);
    p = fmaf(p, f, 1.0f);
    int ik = __float_as_int(kf) - 0x4B400000;
    float scale = __int_as_float((ik + 127) << 23);
    return p * scale;
}

// mma.sync m16n8k16 fp16 -> fp32 (baseline PTX, valid on sm_103)
__device__ __forceinline__ void mma16816(float* c, const uint32_t* a, const uint32_t* b) {
    asm volatile(
        "mma.sync.aligned.m16n8k16.row.col.f32.f16.f16.f32 "
        "{%0,%1,%2,%3}, {%4,%5,%6,%7}, {%8,%9}, {%0,%1,%2,%3};"
        : "+f"(c[0]), "+f"(c[1]), "+f"(c[2]), "+f"(c[3])
        : "r"(a[0]), "r"(a[1]), "r"(a[2]), "r"(a[3]), "r"(b[0]), "r"(b[1]));
}
__device__ __forceinline__ void ldsm_x4(uint32_t* r, uint32_t addr) {
    asm volatile("ldmatrix.sync.aligned.m8n8.x4.shared.b16 {%0,%1,%2,%3}, [%4];"
                 : "=r"(r[0]), "=r"(r[1]), "=r"(r[2]), "=r"(r[3]) : "r"(addr));
}
__device__ __forceinline__ void ldsm_x4_t(uint32_t* r, uint32_t addr) {
    asm volatile("ldmatrix.sync.aligned.m8n8.x4.trans.shared.b16 {%0,%1,%2,%3}, [%4];"
                 : "=r"(r[0]), "=r"(r[1]), "=r"(r[2]), "=r"(r[3]) : "r"(addr));
}
__device__ __forceinline__ uint32_t pack_h2(__half a, __half b) {
    __half2 t = __halves2half2(a, b);
    return *reinterpret_cast<uint32_t*>(&t);
}

// ---------------------------------------------------------------------------
// Kernel 0: convert W (q,k,v) into combined fp16 [CE][192].
// ---------------------------------------------------------------------------
__global__ void wconv_kernel(const float* __restrict__ Wq,
                             const float* __restrict__ Wk,
                             const float* __restrict__ Wv) {
    int i = blockIdx.x * blockDim.x + threadIdx.x;
    if (i >= 3 * CE * HS) return;
    int w = i / (CE * HS);
    int r = i % (CE * HS);
    int k = r / HS;
    int n = r % HS;
    const float* W = (w == 0) ? Wq : (w == 1) ? Wk : Wv;
    g_wh[k * 192 + w * 64 + n] = __float2half_rn(W[k * HS + n]);
}

// ---------------------------------------------------------------------------
// Kernel 1: QKV projection (WMMA fp16, single-term) — R13 verbatim.
// 102400 B smem per CTA -> 2 CTAs/SM co-resident (cross-CTA latency hiding).
// ---------------------------------------------------------------------------
#define AST2 72
#define A_HALFS (128 * AST2)            // 9216 halfs
#define BST 200
#define B_STG (64 * BST)                // 12800 halfs per stage
#define S_OFF_B ((A_HALFS + 2 * B_STG) * 2)   // 69632 bytes
#define P_SMEM_BYTES (S_OFF_B + 128 * 64 * 4) // + 32768 = 102400 B

__global__ __launch_bounds__(384) void qkv_proj_wmma(const float* __restrict__ x)
{
    extern __shared__ __align__(16) char smp[];
    __half* A  = (__half*)smp;
    __half* Bb = A + A_HALFS;
    float*  S  = (float*)(smp + S_OFF_B);

    const int tid = threadIdx.x;
    const int wrp = tid >> 5;
    const int wym = wrp / 3;
    const int wxn = wrp % 3;
    const size_t rowBase = (size_t)blockIdx.x * 128;
    const uint32_t sB = smem_u32(Bb);
    const uint32_t sS = smem_u32(S);

    wmma::fragment<wmma::accumulator, 16, 16, 16, float> acc[2][4];
    #pragma unroll
    for (int i = 0; i < 2; ++i)
        #pragma unroll
        for (int j = 0; j < 4; ++j)
            wmma::fill_fragment(acc[i][j], 0.0f);

    auto issueS = [&](int kc) {
        #pragma unroll
        for (int p = 0; p < 6; ++p) {
            int i = tid + p * 384;             // 2048 float4
            if (i < 2048) {
                int r  = i >> 4;
                int c4 = i & 15;
                cp_async16(sS + (uint32_t)(r * 64 + c4 * 4) * 4,
                           x + (rowBase + r) * CE + kc * 64 + c4 * 4);
            }
        }
    };
    auto issueB = [&](int kc, int st) {
        #pragma unroll
        for (int p = 0; p < 4; ++p) {
            int i = tid + p * 384;             // 1536 x 16B
            int r = i / 24;
            int c = i % 24;
            cp_async16(sB + (uint32_t)(st * B_STG + r * BST + c * 8) * 2,
                       g_wh + (size_t)(kc * 64 + r) * 192 + c * 8);
        }
    };

    issueS(0);
    issueB(0, 0);
    cp_commit();

    for (int kc = 0; kc < 6; ++kc) {
        const int buf = kc & 1;
        cp_wait<0>();
        __syncthreads();       // S(kc), B(kc) resident; prior MMAs done (A free)

        // convert S (fp32) -> A (fp16)
        #pragma unroll
        for (int p = 0; p < 6; ++p) {
            int i = tid + p * 384;
            if (i < 2048) {
                int r  = i >> 4;
                int c4 = i & 15;
                float4 v = *(const float4*)&S[r * 64 + c4 * 4];
                __half* d = A + r * AST2 + c4 * 4;
                ((__half2*)d)[0] = __floats2half2_rn(v.x, v.y);
                ((__half2*)d)[1] = __floats2half2_rn(v.z, v.w);
            }
        }
        __syncthreads();       // A ready; S free
        if (kc < 5) {
            issueS(kc + 1);
            issueB(kc + 1, buf ^ 1);
            cp_commit();       // flies under this chunk's MMAs
        }

        const __half* bS = Bb + buf * B_STG;
        #pragma unroll
        for (int ks = 0; ks < 4; ++ks) {
            wmma::fragment<wmma::matrix_a, 16, 16, 16, __half, wmma::row_major> a[2];
            wmma::fragment<wmma::matrix_b, 16, 16, 16, __half, wmma::row_major> b[4];
            #pragma unroll
            for (int i = 0; i < 2; ++i)
                wmma::load_matrix_sync(a[i], A + (wym * 32 + i * 16) * AST2 + ks * 16, AST2);
            #pragma unroll
            for (int j = 0; j < 4; ++j)
                wmma::load_matrix_sync(b[j], bS + (ks * 16) * BST + wxn * 64 + j * 16, BST);
            #pragma unroll
            for (int i = 0; i < 2; ++i)
                #pragma unroll
                for (int j = 0; j < 4; ++j)
                    wmma::mma_sync(acc[i][j], a[i], b[j], acc[i][j]);
        }
    }

    float* dst = (wxn == 0) ? g_q : (wxn == 1) ? g_k : g_v;
    #pragma unroll
    for (int i = 0; i < 2; ++i) {
        size_t row = rowBase + wym * 32 + i * 16;
        #pragma unroll
        for (int j = 0; j < 4; ++j)
            wmma::store_matrix_sync(dst + row * HS + j * 16, acc[i][j], HS,
                                    wmma::mem_row_major);
    }
}

// ---------------------------------------------------------------------------
// Kernel 2: causal flash attention (split-fp16, raw mma.sync).
// QK^T: 2-term (qh*kh + qh*kl). PV: 1-term (Ph*Vh) — V-lo dropped.
// C layout (rows of KST halfs): kh 0..63 | kl 64..127 | vh 128..191.
// Q staged into rows 0..127 before the key loop (then overwritten).
// __launch_bounds__(256, 2): 2 CTAs/SM for latency hiding.
// ---------------------------------------------------------------------------
#define KST 72
#define C_HALFS (192 * KST)                       // 13824 halfs = 27648 B
#define AS_OFF_B (C_HALFS * 2)                    // byte offset of S
#define ATT_SMEM_BYTES (AS_OFF_B + 8192 * 4)      // 27648 + 32768 = 60416 B

__global__ __launch_bounds__(256, 2) void attn_mma(float* __restrict__ out)
{
    extern __shared__ __align__(16) char smc[];
    __half* C = (__half*)smc;
    float*  S = (float*)(smc + AS_OFF_B);

    const int tid  = threadIdx.x;
    const int lane = tid & 31;
    const int w    = tid >> 5;
    const int b    = blockIdx.y;
    const int qt2  = blockIdx.x;               // 0..1 (128-row q block)
    const int nt   = qt2 * 2 + 2;              // key tiles to process
    const size_t qrow0 = (size_t)b * BT + qt2 * 128;
    const float scale = 0.05103103630798288f;  // 384^-0.5
    const uint32_t sb = smem_u32(C);
    const uint32_t sS = smem_u32(S);

    auto issueS = [&](int st) {
        #pragma unroll
        for (int p = 0; p < 8; ++p) {
            int i   = tid + p * 256;           // 2048 x 16B
            int arr = i >> 10;                 // 0: k, 1: v
            int r   = (i >> 4) & 63;
            int c4  = i & 15;
            const float* src = (arr ? g_v : g_k)
                               + ((size_t)b * BT + st * 64 + r) * HS + c4 * 4;
            cp_async16(sS + (uint32_t)(arr * 4096 + r * 64 + c4 * 4) * 4, src);
        }
        cp_commit();
    };

    issueS(0);   // tile-0 loads in flight while Q stages

    // --- stage Q (direct LDG fp32 -> fp16 hi only, into C rows 0..127) ---
    // 128 rows x 64 floats = 2048 float4 -> 8 iterations x 256 threads
    #pragma unroll
    for (int p = 0; p < 8; ++p) {
        int i  = tid + p * 256;                // 0..2047
        int r  = i >> 4;                       // 0..127
        int c4 = i & 15;
        float4 v = *(const float4*)(g_q + (qrow0 + r) * HS + c4 * 4);
        __half* dh = C + r * KST + c4 * 4;
        ((__half2*)dh)[0] = __floats2half2_rn(v.x, v.y);
        ((__half2*)dh)[1] = __floats2half2_rn(v.z, v.w);
    }
    __syncthreads();

    // --- Q fragments (fp16, held in registers across the whole key loop) ---
    uint32_t qh[4][4];
    const int wrow = w * 16;
    {
        int sub = lane >> 3, r8 = lane & 7;
        int rloc = wrow + (sub & 1) * 8 + r8;
        uint32_t ah_ = sb + (uint32_t)(rloc * KST) * 2 + (sub >> 1) * 16;
        #pragma unroll
        for (int kk = 0; kk < 4; ++kk)
            ldsm_x4(qh[kk], ah_ + kk * 32);
    }
    // (no sync: loop-top sync after cp_wait orders frag reads vs convert writes)

    float o[8][4];
    #pragma unroll
    for (int t = 0; t < 8; ++t)
        #pragma unroll
        for (int i = 0; i < 4; ++i) o[t][i] = 0.0f;
    float m_lo = -1e30f, m_hi = -1e30f, l_lo = 0.0f, l_hi = 0.0f;

    const int growmin = qt2 * 128 + wrow;
    const int growmax = growmin + 15;
    const int grow_lo = growmin + (lane >> 2);
    const int grow_hi = grow_lo + 8;

    const uint32_t kh_b = sb;
    const uint32_t kl_b = sb + (uint32_t)(64 * KST) * 2;
    const uint32_t vh_b = sb + (uint32_t)(128 * KST) * 2;

    for (int st = 0; st < nt; ++st) {
        cp_wait<0>();
        __syncthreads();       // S visible to all; all reads of C done

        // --- convert S (fp32) -> C (kh/kl hi+lo; vh hi only) ---
        #pragma unroll
        for (int p = 0; p < 8; ++p) {
            int i   = tid + p * 256;           // 2048 float4
            int arr = i >> 10;                 // 0: k, 1: v
            int r   = (i >> 4) & 63;
            int c4  = i & 15;
            float4 v = *(const float4*)&S[arr * 4096 + r * 64 + c4 * 4];
            __half* dh = C + (arr * 128 + r) * KST + c4 * 4;
            ((__half2*)dh)[0] = __floats2half2_rn(v.x, v.y);
            ((__half2*)dh)[1] = __floats2half2_rn(v.z, v.w);
            if (arr == 0) {                    // k lo residual
                float hx = __half2float(__float2half_rn(v.x));
                float hy = __half2float(__float2half_rn(v.y));
                float hz = __half2float(__float2half_rn(v.z));
                float hw = __half2float(__float2half_rn(v.w));
                __half* dl = C + (64 + r) * KST + c4 * 4;
                ((__half2*)dl)[0] = __floats2half2_rn(v.x - hx, v.y - hy);
                ((__half2*)dl)[1] = __floats2half2_rn(v.z - hz, v.w - hw);
            }
        }
        __syncthreads();       // C ready; S free
        if (st + 1 < nt) issueS(st + 1);   // loads for next tile fly under compute

        if (st * 64 <= growmax) {
            // --- S = Q K^T (2-term: qh*kh + qh*kl) ---
            float c[8][4];
            #pragma unroll
            for (int t = 0; t < 8; ++t)
                #pragma unroll
                for (int i = 0; i < 4; ++i) c[t][i] = 0.0f;

            {
                int sub = lane >> 3, r8 = lane & 7;
                #pragma unroll
                for (int kk = 0; kk < 4; ++kk) {
                    #pragma unroll
                    for (int tp = 0; tp < 4; ++tp) {
                        int krow = (2 * tp + (sub >> 1)) * 8 + r8;
                        uint32_t off = kk * 32 + (sub & 1) * 16;
                        uint32_t bh4[4], bl4[4];
                        ldsm_x4(bh4, kh_b + (uint32_t)(krow * KST) * 2 + off);
                        ldsm_x4(bl4, kl_b + (uint32_t)(krow * KST) * 2 + off);
                        #pragma unroll
                        for (int tt = 0; tt < 2; ++tt) {
                            int t = 2 * tp + tt;
                            mma16816(c[t], qh[kk], &bh4[2 * tt]);
                            mma16816(c[t], qh[kk], &bl4[2 * tt]);
                        }
                    }
                }
            }

            // --- scale + causal mask ---
            #pragma unroll
            for (int t = 0; t < 8; ++t)
                #pragma unroll
                for (int i = 0; i < 4; ++i) c[t][i] *= scale;

            if (st * 64 + 63 > growmin) {
                int colb = st * 64 + 2 * (lane & 3);
                #pragma unroll
                for (int t = 0; t < 8; ++t) {
                    int c0 = colb + 8 * t, c1 = c0 + 1;
                    if (c0 > grow_lo) c[t][0] = -1e30f;
                    if (c1 > grow_lo) c[t][1] = -1e30f;
                    if (c0 > grow_hi) c[t][2] = -1e30f;
                    if (c1 > grow_hi) c[t][3] = -1e30f;
                }
            }

            // --- online softmax in registers ---
            float mx0 = -1e30f, mx1 = -1e30f;
            #pragma unroll
            for (int t = 0; t < 8; ++t) {
                mx0 = fmaxf(mx0, fmaxf(c[t][0], c[t][1]));
                mx1 = fmaxf(mx1, fmaxf(c[t][2], c[t][3]));
            }
            mx0 = fmaxf(mx0, __shfl_xor_sync(0xffffffffu, mx0, 1, 4));
            mx0 = fmaxf(mx0, __shfl_xor_sync(0xffffffffu, mx0, 2, 4));
            mx1 = fmaxf(mx1, __shfl_xor_sync(0xffffffffu, mx1, 1, 4));
            mx1 = fmaxf(mx1, __shfl_xor_sync(0xffffffffu, mx1, 2, 4));
            float mn0 = fmaxf(m_lo, mx0), mn1 = fmaxf(m_hi, mx1);
            float al0 = fast_exp(m_lo - mn0), al1 = fast_exp(m_hi - mn1);
            m_lo = mn0; m_hi = mn1;

            float s0 = 0.0f, s1 = 0.0f;
            #pragma unroll
            for (int t = 0; t < 8; ++t) {
                c[t][0] = fast_exp(c[t][0] - mn0); s0 += c[t][0];
                c[t][1] = fast_exp(c[t][1] - mn0); s0 += c[t][1];
                c[t][2] = fast_exp(c[t][2] - mn1); s1 += c[t][2];
                c[t][3] = fast_exp(c[t][3] - mn1); s1 += c[t][3];
            }
            s0 += __shfl_xor_sync(0xffffffffu, s0, 1, 4);
            s0 += __shfl_xor_sync(0xffffffffu, s0, 2, 4);
            s1 += __shfl_xor_sync(0xffffffffu, s1, 1, 4);
            s1 += __shfl_xor_sync(0xffffffffu, s1, 2, 4);
            l_lo = l_lo * al0 + s0;
            l_hi = l_hi * al1 + s1;
            #pragma unroll
            for (int t = 0; t < 8; ++t) {
                o[t][0] *= al0; o[t][1] *= al0;
                o[t][2] *= al1; o[t][3] *= al1;
            }

            // --- O += P V (1-term: Ph*Vh) ---
            {
                int sub = lane >> 3, r8 = lane & 7;
                #pragma unroll
                for (int kv = 0; kv < 4; ++kv) {
                    uint32_t af_h[4];
                    #pragma unroll
                    for (int half = 0; half < 2; ++half) {
                        int tt = 2 * kv + half;
                        af_h[half * 2 + 0] = pack_h2(__float2half_rn(c[tt][0]),
                                                     __float2half_rn(c[tt][1]));
                        af_h[half * 2 + 1] = pack_h2(__float2half_rn(c[tt][2]),
                                                     __float2half_rn(c[tt][3]));
                    }

                    int vrow = kv * 16 + (sub & 1) * 8 + r8;
                    #pragma unroll
                    for (int tp = 0; tp < 4; ++tp) {
                        uint32_t off = 16 * (2 * tp + (sub >> 1));
                        uint32_t vh4[4];
                        ldsm_x4_t(vh4, vh_b + (uint32_t)(vrow * KST) * 2 + off);
                        #pragma unroll
                        for (int tt = 0; tt < 2; ++tt) {
                            int t = 2 * tp + tt;
                            mma16816(o[t], af_h, &vh4[2 * tt]);
                        }
                    }
                }
            }
        }
    }

    // --- epilogue: normalize by 1/l, write out ---
    float inv0 = 1.0f / l_lo, inv1 = 1.0f / l_hi;
    int rlo = wrow + (lane >> 2);
    size_t base_lo = (qrow0 + rlo) * HS + 2 * (lane & 3);
    size_t base_hi = (qrow0 + rlo + 8) * HS + 2 * (lane & 3);
    #pragma unroll
    for (int t = 0; t < 8; ++t) {
        *(float2*)(out + base_lo + 8 * t) = make_float2(o[t][0] * inv0, o[t][1] * inv0);
        *(float2*)(out + base_hi + 8 * t) = make_float2(o[t][2] * inv1, o[t][3] * inv1);
    }
}

// ---------------------------------------------------------------------------
// Launch
// ---------------------------------------------------------------------------
extern "C" void kernel_launch(void* const* d_in, const int* in_sizes, int n_in,
                              void* d_out, int out_size)
{
    (void)in_sizes; (void)n_in; (void)out_size;
    const float* x  = (const float*)d_in[0];
    const float* Wq = (const float*)d_in[1];
    const float* Wk = (const float*)d_in[2];
    const float* Wv = (const float*)d_in[3];
    float* out = (float*)d_out;

    cudaFuncSetAttribute(qkv_proj_wmma,
                         cudaFuncAttributeMaxDynamicSharedMemorySize,
                         P_SMEM_BYTES);
    cudaFuncSetAttribute(attn_mma,
                         cudaFuncAttributeMaxDynamicSharedMemorySize,
                         ATT_SMEM_BYTES);

    // W -> combined fp16
    wconv_kernel<<<(3 * CE * HS + 255) / 256, 256>>>(Wq, Wk, Wv);

    // QKV projection on tensor cores: 262144 rows / 128 per CTA = 2048 CTAs
    qkv_proj_wmma<<<2048, 384, P_SMEM_BYTES>>>(x);

    // Attention: 2 q-blocks of 128 rows x 1024 batches
    attn_mma<<<dim3(2, NB), 256, ATT_SMEM_BYTES>>>(out);
}